// round 9
// baseline (speedup 1.0000x reference)
#include <cuda_runtime.h>
#include <cuda_bf16.h>
#include <cstdint>

#define BB 256
#define LL 1024
#define TT 128
#define GRID 152

// ---------------------------------------------------------------------------
// One fused kernel. Per CTA:
//   - sniff index dtype (int32 vs int64) from sequence_lengths layout
//   - build LPT schedule locally (rank by counting; no globals, no atomics)
//   - per batch: sequence score (gather) + forward recursion
// Recursion state: raw stabilized dot 'acc' — no log/exp on the critical path.
// Dot product in bf16 HFMA2 (2 MACs/instr). Input rows prefetched through a
// 4-deep register FIFO so the ~577-cyc DRAM latency never hits the chain.
// ---------------------------------------------------------------------------
__global__ void __launch_bounds__(128)
crf_all(const float* __restrict__ inputs,
        const int*   __restrict__ tags32,
        const int*   __restrict__ slen32,
        const float* __restrict__ trans,
        float* __restrict__ out)
{
    const int t = threadIdx.x;

    // int64 layout => odd words of seqlen are high words (0); int32 => >=1.
    const int stride = ((slen32[1] | slen32[3] | slen32[5] | slen32[7]) == 0) ? 2 : 1;

    __shared__ int slen[BB];
    __shared__ int inv[BB];                            // inv[rank] = batch id
    __shared__ __align__(16) __nv_bfloat16 sh_ea[2][TT];  // stabilized alphas
    __shared__ float sh_d[2];                          // offset increment bcast
    __shared__ float sh_red[TT];                       // reduction scratch

    for (int i = t; i < BB; i += 128) {
        int v = slen32[(size_t)i * stride];
        if (v < 1) v = 1; if (v > LL) v = LL;
        slen[i] = v;
    }
    __syncthreads();

    // local LPT schedule: rank batches by descending length (unique keys)
    for (int i = t; i < BB; i += 128) {
        unsigned key_i = ((unsigned)(slen[i]) << 8) | (unsigned)i;
        int r = 0;
        for (int j = 0; j < BB; j++) {
            unsigned key_j = ((unsigned)(slen[j]) << 8) | (unsigned)j;
            r += (key_j > key_i) ? 1 : 0;
        }
        inv[r] = i;
    }

    // exp(trans) column for this thread's tag, packed bf16x2 (64 regs)
    __nv_bfloat162 eT2[TT / 2];
    #pragma unroll
    for (int k = 0; k < TT / 2; k++) {
        float e0 = __expf(trans[(2 * k + 0) * TT + t]);
        float e1 = __expf(trans[(2 * k + 1) * TT + t]);
        eT2[k] = __floats2bfloat162_rn(e0, e1);
    }
    __syncthreads();                                   // inv[] ready

    // static schedule: CTA i -> rank i; CTAs 0..(BB-1-GRID) also -> rank 255-i
    const int nb = ((int)blockIdx.x <= BB - 1 - GRID) ? 2 : 1;

    for (int q = 0; q < nb; q++) {
        int rank = (q == 0) ? (int)blockIdx.x : (BB - 1 - (int)blockIdx.x);
        int b = inv[rank];
        int len = slen[b];
        int nsteps = len - 1; if (nsteps < 1) nsteps = 1;
        const float* inp = inputs + (size_t)b * LL * TT;
        const int*   tg  = tags32 + (size_t)b * LL * stride;

        // ---- sequence score: unary + transition gathers, masked ----
        float s = 0.f;
        for (int l = t; l < len; l += 128) {
            int cur = tg[(size_t)l * stride] & (TT - 1);
            s += inp[(size_t)l * TT + cur];
            if (l > 0) {
                int prev = tg[(size_t)(l - 1) * stride] & (TT - 1);
                s += trans[prev * TT + cur];
            }
        }
        sh_red[t] = s;
        __syncthreads();
        for (int o = 64; o > 0; o >>= 1) {
            if (t < o) sh_red[t] += sh_red[t + o];
            __syncthreads();
        }
        float seqscore = sh_red[0];
        __syncthreads();                               // WAR guard on sh_red

        // ---- forward recursion (log-free critical path, bf16 dot) ----
        float M0 = inp[0];                             // broadcast offset M(0)
        float Msum = M0;                               // absolute offset accum
        float ea_f = __expf(inp[t] - M0);              // exp(alpha(0) - M(0))
        float d_local = 0.f;                           // d(0) (thread 0's)
        int buf = 0;

        // 4-deep input-row prefetch FIFO: f0 = row l, f3 = row l+3
        float f0 = inp[(size_t)1 * TT + t];            // L=1024, rows 1..4 exist
        float f1 = inp[(size_t)2 * TT + t];
        float f2 = inp[(size_t)3 * TT + t];
        float f3 = inp[(size_t)4 * TT + t];

        for (int l = 1; l <= nsteps; l++) {
            float inp_cur = f0;
            sh_ea[buf][t] = __float2bfloat16(ea_f);
            if (t == 0) sh_d[buf] = d_local;           // d(l-1)
            // rotate FIFO and issue prefetch of row l+4 (consumed 4 steps out)
            f0 = f1; f1 = f2; f2 = f3;
            int nrow = (l + 4 < LL) ? l + 4 : LL - 1;
            f3 = inp[(size_t)nrow * TT + t];
            __syncthreads();
            float d_prev = sh_d[buf];
            float e_t = __expf(inp_cur - d_prev);      // hides under dot issue

            const uint4* ev = reinterpret_cast<const uint4*>(sh_ea[buf]);
            __nv_bfloat162 zz = __floats2bfloat162_rn(0.f, 0.f);
            __nv_bfloat162 a0 = zz, a1 = zz, a2 = zz, a3 = zz;
            #pragma unroll
            for (int k = 0; k < TT / 8; k++) {         // 16 LDS.128 + 64 HFMA2
                uint4 e = ev[k];
                a0 = __hfma2(*reinterpret_cast<__nv_bfloat162*>(&e.x),
                             eT2[4 * k + 0], a0);
                a1 = __hfma2(*reinterpret_cast<__nv_bfloat162*>(&e.y),
                             eT2[4 * k + 1], a1);
                a2 = __hfma2(*reinterpret_cast<__nv_bfloat162*>(&e.z),
                             eT2[4 * k + 2], a2);
                a3 = __hfma2(*reinterpret_cast<__nv_bfloat162*>(&e.w),
                             eT2[4 * k + 3], a3);
            }
            // fp32 combine of the 8 bf16 partial lanes
            float2 g0 = __bfloat1622float2(a0);
            float2 g1 = __bfloat1622float2(a1);
            float2 g2 = __bfloat1622float2(a2);
            float2 g3 = __bfloat1622float2(a3);
            float acc = ((g0.x + g0.y) + (g1.x + g1.y))
                      + ((g2.x + g2.y) + (g3.x + g3.y));

            ea_f = acc * e_t;                          // exp(alpha(l) - M(l))
            if (t == 0)                                // d(l) from exponent bits
                d_local = inp_cur + 0.6931471805599453f *
                          (float)((int)(__float_as_uint(acc) >> 23) - 127);
            Msum += d_prev;                            // M(l) running total
            buf ^= 1;
        }

        // ---- log_norm = M(ns) + ln(sum_t ea_t), fp32 reduction ----
        sh_red[t] = ea_f;
        __syncthreads();
        for (int o = 64; o > 0; o >>= 1) {
            if (t < o) sh_red[t] += sh_red[t + o];
            __syncthreads();
        }
        if (t == 0) out[b] = seqscore - (Msum + __logf(sh_red[0]));
        __syncthreads();                               // protect shared
    }
}

// ---------------------------------------------------------------------------
extern "C" void kernel_launch(void* const* d_in, const int* in_sizes, int n_in,
                              void* d_out, int out_size) {
    const float* inputs = (const float*)d_in[0];
    const int*   tags32 = (const int*)d_in[1];
    const int*   slen32 = (const int*)d_in[2];
    const float* trans  = (const float*)d_in[3];
    float* outp = (float*)d_out;

    crf_all<<<GRID, 128>>>(inputs, tags32, slen32, trans, outp);
}

// round 10
// speedup vs baseline: 1.0157x; 1.0157x over previous
#include <cuda_runtime.h>
#include <cuda_bf16.h>
#include <cstdint>

#define BB 256
#define LL 1024
#define TT 128
#define GRID 152

// ---------------------------------------------------------------------------
// One fused kernel. Per CTA:
//   - sniff index dtype (int32 vs int64) from sequence_lengths layout
//   - build LPT schedule locally (rank by counting; no globals, no atomics)
//   - per batch: sequence score (gather) + forward recursion
// Recursion state: raw stabilized dot 'acc' — no log/exp on the critical path.
// Dot in bf16 HFMA2. Step loop unrolled x4 with one dedicated prefetch
// register per sub-step -> input LDG consumed at TRUE distance 4 (~1000 cyc),
// fully hiding DRAM latency (round-9 FIFO rotation collapsed it to dist 1).
// ---------------------------------------------------------------------------
__global__ void __launch_bounds__(128)
crf_all(const float* __restrict__ inputs,
        const int*   __restrict__ tags32,
        const int*   __restrict__ slen32,
        const float* __restrict__ trans,
        float* __restrict__ out)
{
    const int t = threadIdx.x;

    // int64 layout => odd words of seqlen are high words (0); int32 => >=1.
    const int stride = ((slen32[1] | slen32[3] | slen32[5] | slen32[7]) == 0) ? 2 : 1;

    __shared__ int slen[BB];
    __shared__ int inv[BB];                            // inv[rank] = batch id
    __shared__ __align__(16) __nv_bfloat16 sh_ea[2][TT];  // stabilized alphas
    __shared__ float sh_d[2];                          // offset increment bcast
    __shared__ float sh_red[TT];                       // reduction scratch

    for (int i = t; i < BB; i += 128) {
        int v = slen32[(size_t)i * stride];
        if (v < 1) v = 1; if (v > LL) v = LL;
        slen[i] = v;
    }
    __syncthreads();

    // local LPT schedule: rank batches by descending length (unique keys)
    for (int i = t; i < BB; i += 128) {
        unsigned key_i = ((unsigned)(slen[i]) << 8) | (unsigned)i;
        int r = 0;
        for (int j = 0; j < BB; j++) {
            unsigned key_j = ((unsigned)(slen[j]) << 8) | (unsigned)j;
            r += (key_j > key_i) ? 1 : 0;
        }
        inv[r] = i;
    }

    // exp(trans) column for this thread's tag, packed bf16x2 (64 regs)
    __nv_bfloat162 eT2[TT / 2];
    #pragma unroll
    for (int k = 0; k < TT / 2; k++) {
        float e0 = __expf(trans[(2 * k + 0) * TT + t]);
        float e1 = __expf(trans[(2 * k + 1) * TT + t]);
        eT2[k] = __floats2bfloat162_rn(e0, e1);
    }
    __syncthreads();                                   // inv[] ready

    // static schedule: CTA i -> rank i; CTAs 0..(BB-1-GRID) also -> rank 255-i
    const int nb = ((int)blockIdx.x <= BB - 1 - GRID) ? 2 : 1;

    for (int q = 0; q < nb; q++) {
        int rank = (q == 0) ? (int)blockIdx.x : (BB - 1 - (int)blockIdx.x);
        int b = inv[rank];
        int len = slen[b];
        int nsteps = len - 1; if (nsteps < 1) nsteps = 1;
        const float* inp = inputs + (size_t)b * LL * TT;
        const int*   tg  = tags32 + (size_t)b * LL * stride;

        // ---- sequence score: unary + transition gathers, masked ----
        float s = 0.f;
        for (int l = t; l < len; l += 128) {
            int cur = tg[(size_t)l * stride] & (TT - 1);
            s += inp[(size_t)l * TT + cur];
            if (l > 0) {
                int prev = tg[(size_t)(l - 1) * stride] & (TT - 1);
                s += trans[prev * TT + cur];
            }
        }
        sh_red[t] = s;
        __syncthreads();
        for (int o = 64; o > 0; o >>= 1) {
            if (t < o) sh_red[t] += sh_red[t + o];
            __syncthreads();
        }
        float seqscore = sh_red[0];
        __syncthreads();                               // WAR guard on sh_red

        // ---- forward recursion (log-free critical path, bf16 dot) ----
        float M0 = inp[0];                             // broadcast offset M(0)
        float Msum = M0;                               // absolute offset accum
        float ea_f = __expf(inp[t] - M0);              // exp(alpha(0) - M(0))
        float d_local = 0.f;                           // d(0) (thread 0's)

        // dedicated prefetch regs: f_j holds row (l0 + j) at block top
        float pf0 = inp[(size_t)1 * TT + t];
        float pf1 = inp[(size_t)2 * TT + t];
        float pf2 = inp[(size_t)3 * TT + t];
        float pf3 = inp[(size_t)4 * TT + t];

        // one sub-step; fj consumed now, reloaded for step l+4 (true dist 4)
        #define CRF_STEP(J, BUFC, FREG)                                        \
        {                                                                      \
            const int l = l0 + (J);                                            \
            float inp_cur = FREG;                                              \
            sh_ea[BUFC][t] = __float2bfloat16(ea_f);                           \
            if (t == 0) sh_d[BUFC] = d_local;                                  \
            int nrow = (l + 4 < LL) ? l + 4 : LL - 1;                          \
            FREG = inp[(size_t)nrow * TT + t];                                 \
            __syncthreads();                                                   \
            float d_prev = sh_d[BUFC];                                         \
            float e_t = __expf(inp_cur - d_prev);                              \
            const uint4* ev = reinterpret_cast<const uint4*>(sh_ea[BUFC]);     \
            __nv_bfloat162 zz = __floats2bfloat162_rn(0.f, 0.f);               \
            __nv_bfloat162 a0 = zz, a1 = zz, a2 = zz, a3 = zz;                 \
            _Pragma("unroll")                                                  \
            for (int k = 0; k < TT / 8; k++) {                                 \
                uint4 e = ev[k];                                               \
                a0 = __hfma2(*reinterpret_cast<__nv_bfloat162*>(&e.x),         \
                             eT2[4 * k + 0], a0);                              \
                a1 = __hfma2(*reinterpret_cast<__nv_bfloat162*>(&e.y),         \
                             eT2[4 * k + 1], a1);                              \
                a2 = __hfma2(*reinterpret_cast<__nv_bfloat162*>(&e.z),         \
                             eT2[4 * k + 2], a2);                              \
                a3 = __hfma2(*reinterpret_cast<__nv_bfloat162*>(&e.w),         \
                             eT2[4 * k + 3], a3);                              \
            }                                                                  \
            float2 g0 = __bfloat1622float2(a0);                                \
            float2 g1 = __bfloat1622float2(a1);                                \
            float2 g2 = __bfloat1622float2(a2);                                \
            float2 g3 = __bfloat1622float2(a3);                                \
            float acc = ((g0.x + g0.y) + (g1.x + g1.y))                        \
                      + ((g2.x + g2.y) + (g3.x + g3.y));                       \
            if (l <= nsteps) {                      /* uniform predicate */    \
                ea_f = acc * e_t;                                              \
                if (t == 0)                                                    \
                    d_local = inp_cur + 0.6931471805599453f *                  \
                        (float)((int)(__float_as_uint(acc) >> 23) - 127);      \
                Msum += d_prev;                                                \
            }                                                                  \
        }

        for (int l0 = 1; l0 <= nsteps; l0 += 4) {
            CRF_STEP(0, 0, pf0)
            CRF_STEP(1, 1, pf1)
            CRF_STEP(2, 0, pf2)
            CRF_STEP(3, 1, pf3)
        }
        #undef CRF_STEP

        // ---- log_norm = M(ns) + ln(sum_t ea_t), fp32 reduction ----
        sh_red[t] = ea_f;
        __syncthreads();
        for (int o = 64; o > 0; o >>= 1) {
            if (t < o) sh_red[t] += sh_red[t + o];
            __syncthreads();
        }
        if (t == 0) out[b] = seqscore - (Msum + __logf(sh_red[0]));
        __syncthreads();                               // protect shared
    }
}

// ---------------------------------------------------------------------------
extern "C" void kernel_launch(void* const* d_in, const int* in_sizes, int n_in,
                              void* d_out, int out_size) {
    const float* inputs = (const float*)d_in[0];
    const int*   tags32 = (const int*)d_in[1];
    const int*   slen32 = (const int*)d_in[2];
    const float* trans  = (const float*)d_in[3];
    float* outp = (float*)d_out;

    crf_all<<<GRID, 128>>>(inputs, tags32, slen32, trans, outp);
}

// round 11
// speedup vs baseline: 1.5177x; 1.4942x over previous
#include <cuda_runtime.h>
#include <cuda_bf16.h>
#include <cstdint>

#define BB 256
#define LL 1024
#define TT 128
#define GRID 148

// ---------------------------------------------------------------------------
// One fused kernel. Per CTA:
//   - sniff index dtype (int32 vs int64) from sequence_lengths layout
//   - build LPT schedule locally (rank by counting; no globals, no atomics)
//   - per batch: sequence score (gather) + forward recursion
// Recursion (branchless critical path):
//   ea_t = exp(alpha_t - M), M = M0 + ln2*Etot (Etot exact integer).
//   Per step: acc_t = sum_s ea_s * expT[s][t]  (bf16 HFMA2 dot),
//   E = bf16-exponent of ea[0] (read from the first LDS.128 -> identical in
//   every thread; no t==0 branch, no broadcast round-trip),
//   ea_t' = acc_t * exp(inp_t) * 2^-E,  Etot += E.
//   bf16 store via integer round-to-nearest (no F2FP on the chain).
//   Unroll x8 with one dedicated prefetch register per sub-step (dist 8).
// ---------------------------------------------------------------------------
__global__ void __launch_bounds__(128)
crf_all(const float* __restrict__ inputs,
        const int*   __restrict__ tags32,
        const int*   __restrict__ slen32,
        const float* __restrict__ trans,
        float* __restrict__ out)
{
    const int t = threadIdx.x;

    // int64 layout => odd words of seqlen are high words (0); int32 => >=1.
    const int stride = ((slen32[1] | slen32[3] | slen32[5] | slen32[7]) == 0) ? 2 : 1;

    __shared__ int slen[BB];
    __shared__ int inv[BB];                              // inv[rank] = batch id
    __shared__ __align__(16) unsigned short sh_ea[2][TT];  // bf16 stabilized alphas
    __shared__ float sh_red[TT];                         // reduction scratch

    for (int i = t; i < BB; i += 128) {
        int v = slen32[(size_t)i * stride];
        if (v < 1) v = 1; if (v > LL) v = LL;
        slen[i] = v;
    }
    __syncthreads();

    // local LPT schedule: rank batches by descending length (unique keys)
    for (int i = t; i < BB; i += 128) {
        unsigned key_i = ((unsigned)(slen[i]) << 8) | (unsigned)i;
        int r = 0;
        for (int j = 0; j < BB; j++) {
            unsigned key_j = ((unsigned)(slen[j]) << 8) | (unsigned)j;
            r += (key_j > key_i) ? 1 : 0;
        }
        inv[r] = i;
    }

    // exp(trans) column for this thread's tag, packed bf16x2 (64 regs)
    __nv_bfloat162 eT2[TT / 2];
    #pragma unroll
    for (int k = 0; k < TT / 2; k++) {
        float e0 = __expf(trans[(2 * k + 0) * TT + t]);
        float e1 = __expf(trans[(2 * k + 1) * TT + t]);
        eT2[k] = __floats2bfloat162_rn(e0, e1);
    }
    __syncthreads();                                     // inv[] ready

    // static schedule: CTA i -> rank i; CTAs 0..(BB-1-GRID) also -> rank 255-i
    const int nb = ((int)blockIdx.x <= BB - 1 - GRID) ? 2 : 1;

    for (int q = 0; q < nb; q++) {
        int rank = (q == 0) ? (int)blockIdx.x : (BB - 1 - (int)blockIdx.x);
        int b = inv[rank];
        int len = slen[b];
        int nsteps = len - 1; if (nsteps < 1) nsteps = 1;
        const float* inp = inputs + (size_t)b * LL * TT;
        const int*   tg  = tags32 + (size_t)b * LL * stride;

        // ---- sequence score: unary + transition gathers, masked ----
        float s = 0.f;
        for (int l = t; l < len; l += 128) {
            int cur = tg[(size_t)l * stride] & (TT - 1);
            s += inp[(size_t)l * TT + cur];
            if (l > 0) {
                int prev = tg[(size_t)(l - 1) * stride] & (TT - 1);
                s += trans[prev * TT + cur];
            }
        }
        sh_red[t] = s;
        __syncthreads();
        for (int o = 64; o > 0; o >>= 1) {
            if (t < o) sh_red[t] += sh_red[t + o];
            __syncthreads();
        }
        float seqscore = sh_red[0];
        __syncthreads();                                 // WAR guard on sh_red

        // ---- forward recursion ----
        float M0 = inp[0];                               // broadcast offset
        float ea_f = __expf(inp[t] - M0);                // exp(alpha(0) - M0)
        int Etot = 0;                                    // exact offset (ln2 units)

        // dedicated prefetch regs: pfJ holds row (l0 + J) at block top
        float pf0 = inp[(size_t)1 * TT + t];
        float pf1 = inp[(size_t)2 * TT + t];
        float pf2 = inp[(size_t)3 * TT + t];
        float pf3 = inp[(size_t)4 * TT + t];
        float pf4 = inp[(size_t)5 * TT + t];
        float pf5 = inp[(size_t)6 * TT + t];
        float pf6 = inp[(size_t)7 * TT + t];
        float pf7 = inp[(size_t)8 * TT + t];

        #define CRF_STEP(J, BUFC, FREG)                                        \
        {                                                                      \
            const int l = l0 + (J);                                            \
            float inp_cur = FREG;                                              \
            /* bf16 round-to-nearest via integer (no F2FP on chain) */         \
            unsigned ub = __float_as_uint(ea_f);                               \
            sh_ea[BUFC][t] = (unsigned short)((ub + 0x8000u) >> 16);           \
            int nrow = (l + 8 < LL) ? l + 8 : LL - 1;                          \
            FREG = inp[(size_t)nrow * TT + t];   /* consumed 8 steps out */    \
            __syncthreads();                                                   \
            float e_t = __expf(inp_cur);                                       \
            const uint4* ev = reinterpret_cast<const uint4*>(sh_ea[BUFC]);     \
            uint4 e0q = ev[0];                                                 \
            /* CTA-uniform renorm: E = bf16 exponent of ea[0] */               \
            int E = (int)((e0q.x >> 7) & 0xFFu) - 127;                         \
            float sE = __uint_as_float((unsigned)(127 - E) << 23);             \
            __nv_bfloat162 zz = __floats2bfloat162_rn(0.f, 0.f);               \
            __nv_bfloat162 a0 = zz, a1 = zz, a2 = zz, a3 = zz;                 \
            a0 = __hfma2(*reinterpret_cast<__nv_bfloat162*>(&e0q.x),           \
                         eT2[0], a0);                                          \
            a1 = __hfma2(*reinterpret_cast<__nv_bfloat162*>(&e0q.y),           \
                         eT2[1], a1);                                          \
            a2 = __hfma2(*reinterpret_cast<__nv_bfloat162*>(&e0q.z),           \
                         eT2[2], a2);                                          \
            a3 = __hfma2(*reinterpret_cast<__nv_bfloat162*>(&e0q.w),           \
                         eT2[3], a3);                                          \
            _Pragma("unroll")                                                  \
            for (int k = 1; k < TT / 8; k++) {                                 \
                uint4 e = ev[k];                                               \
                a0 = __hfma2(*reinterpret_cast<__nv_bfloat162*>(&e.x),         \
                             eT2[4 * k + 0], a0);                              \
                a1 = __hfma2(*reinterpret_cast<__nv_bfloat162*>(&e.y),         \
                             eT2[4 * k + 1], a1);                              \
                a2 = __hfma2(*reinterpret_cast<__nv_bfloat162*>(&e.z),         \
                             eT2[4 * k + 2], a2);                              \
                a3 = __hfma2(*reinterpret_cast<__nv_bfloat162*>(&e.w),         \
                             eT2[4 * k + 3], a3);                              \
            }                                                                  \
            float2 g0 = __bfloat1622float2(a0);                                \
            float2 g1 = __bfloat1622float2(a1);                                \
            float2 g2 = __bfloat1622float2(a2);                                \
            float2 g3 = __bfloat1622float2(a3);                                \
            float acc = ((g0.x + g0.y) + (g1.x + g1.y))                        \
                      + ((g2.x + g2.y) + (g3.x + g3.y));                       \
            float ea_new = acc * e_t * sE;                                     \
            bool live = (l <= nsteps);          /* uniform -> FSEL/SEL */      \
            ea_f = live ? ea_new : ea_f;                                       \
            Etot += live ? E : 0;                                              \
        }

        for (int l0 = 1; l0 <= nsteps; l0 += 8) {
            CRF_STEP(0, 0, pf0)
            CRF_STEP(1, 1, pf1)
            CRF_STEP(2, 0, pf2)
            CRF_STEP(3, 1, pf3)
            CRF_STEP(4, 0, pf4)
            CRF_STEP(5, 1, pf5)
            CRF_STEP(6, 0, pf6)
            CRF_STEP(7, 1, pf7)
        }
        #undef CRF_STEP

        // ---- log_norm = M0 + Etot*ln2 + ln(sum_t ea_t) ----
        sh_red[t] = ea_f;
        __syncthreads();
        for (int o = 64; o > 0; o >>= 1) {
            if (t < o) sh_red[t] += sh_red[t + o];
            __syncthreads();
        }
        if (t == 0)
            out[b] = seqscore -
                     (M0 + 0.6931471805599453f * (float)Etot + __logf(sh_red[0]));
        __syncthreads();                                 // protect shared
    }
}

// ---------------------------------------------------------------------------
extern "C" void kernel_launch(void* const* d_in, const int* in_sizes, int n_in,
                              void* d_out, int out_size) {
    const float* inputs = (const float*)d_in[0];
    const int*   tags32 = (const int*)d_in[1];
    const int*   slen32 = (const int*)d_in[2];
    const float* trans  = (const float*)d_in[3];
    float* outp = (float*)d_out;

    crf_all<<<GRID, 128>>>(inputs, tags32, slen32, trans, outp);
}

// round 14
// speedup vs baseline: 1.8599x; 1.2255x over previous
#include <cuda_runtime.h>
#include <cuda_bf16.h>
#include <cstdint>

#define BB 256
#define LL 1024
#define TT 128
#define GRID 148

// ---------------------------------------------------------------------------
// One fused kernel. Per CTA:
//   - sniff index dtype (int32 vs int64) from sequence_lengths layout
//   - build LPT schedule locally (rank by counting; no globals, no atomics)
//   - per batch: sequence score (gather) + forward recursion
// Recursion (branchless, stripped critical path):
//   ea_t = exp(alpha_t - M), M = M0 + ln2*Etot (exact integer Etot).
//   Per step: 16 front-batched LDS.128 -> 64 HFMA2 (bf16) -> HADD2 tree ->
//   ea' = acc * e_t * 2^-E,  E = bf16 exponent of ea[0] (CTA-uniform).
//   e_t comes from a two-stage FIFO: LDG at distance 16, EX2 at distance 8,
//   so neither DRAM nor MUFU latency ever touches the serial chain.
//   Main loop = full unroll-8 blocks (no guards); scalar epilogue for tail.
// ---------------------------------------------------------------------------
__global__ void __launch_bounds__(128)
crf_all(const float* __restrict__ inputs,
        const int*   __restrict__ tags32,
        const int*   __restrict__ slen32,
        const float* __restrict__ trans,
        float* __restrict__ out)
{
    const int t = threadIdx.x;

    // int64 layout => odd words of seqlen are high words (0); int32 => >=1.
    const int stride = ((slen32[1] | slen32[3] | slen32[5] | slen32[7]) == 0) ? 2 : 1;

    __shared__ int slen[BB];
    __shared__ int inv[BB];                               // inv[rank] = batch id
    __shared__ __align__(16) unsigned short sh_ea[2][TT]; // bf16 stabilized alphas
    __shared__ float sh_red[TT];                          // reduction scratch

    for (int i = t; i < BB; i += 128) {
        int v = slen32[(size_t)i * stride];
        if (v < 1) v = 1; if (v > LL) v = LL;
        slen[i] = v;
    }
    __syncthreads();

    // local LPT schedule: rank batches by descending length (unique keys)
    for (int i = t; i < BB; i += 128) {
        unsigned key_i = ((unsigned)(slen[i]) << 8) | (unsigned)i;
        int r = 0;
        for (int j = 0; j < BB; j++) {
            unsigned key_j = ((unsigned)(slen[j]) << 8) | (unsigned)j;
            r += (key_j > key_i) ? 1 : 0;
        }
        inv[r] = i;
    }

    // exp(trans) column for this thread's tag, packed bf16x2 (64 regs)
    __nv_bfloat162 eT2[TT / 2];
    #pragma unroll
    for (int k = 0; k < TT / 2; k++) {
        float e0 = __expf(trans[(2 * k + 0) * TT + t]);
        float e1 = __expf(trans[(2 * k + 1) * TT + t]);
        eT2[k] = __floats2bfloat162_rn(e0, e1);
    }
    __syncthreads();                                      // inv[] ready

    // static schedule: CTA i -> rank i; CTAs 0..(BB-1-GRID) also -> rank 255-i
    const int nb = ((int)blockIdx.x <= BB - 1 - GRID) ? 2 : 1;

    for (int q = 0; q < nb; q++) {
        int rank = (q == 0) ? (int)blockIdx.x : (BB - 1 - (int)blockIdx.x);
        int b = inv[rank];
        int len = slen[b];
        int nsteps = len - 1; if (nsteps < 1) nsteps = 1;
        const float* inp = inputs + (size_t)b * LL * TT;
        const int*   tg  = tags32 + (size_t)b * LL * stride;

        // ---- sequence score: unary + transition gathers, masked ----
        float s = 0.f;
        for (int l = t; l < len; l += 128) {
            int cur = tg[(size_t)l * stride] & (TT - 1);
            s += inp[(size_t)l * TT + cur];
            if (l > 0) {
                int prev = tg[(size_t)(l - 1) * stride] & (TT - 1);
                s += trans[prev * TT + cur];
            }
        }
        sh_red[t] = s;
        __syncthreads();
        for (int o = 64; o > 0; o >>= 1) {
            if (t < o) sh_red[t] += sh_red[t + o];
            __syncthreads();
        }
        float seqscore = sh_red[0];
        __syncthreads();                                  // WAR guard on sh_red

        // ---- forward recursion ----
        float M0 = inp[0];
        float ea_f = __expf(inp[t] - M0);                 // exp(alpha(0) - M0)
        int Etot = 0;
        const float* pin = inp + t;

        // two-stage FIFO: eJ = exp(input row (l0+J)); rawJ = raw row (l0+J+8)
        float e0 = __expf(pin[(size_t)1 * TT]);
        float e1 = __expf(pin[(size_t)2 * TT]);
        float e2 = __expf(pin[(size_t)3 * TT]);
        float e3 = __expf(pin[(size_t)4 * TT]);
        float e4 = __expf(pin[(size_t)5 * TT]);
        float e5 = __expf(pin[(size_t)6 * TT]);
        float e6 = __expf(pin[(size_t)7 * TT]);
        float e7 = __expf(pin[(size_t)8 * TT]);
        float r0 = pin[(size_t)9  * TT];
        float r1 = pin[(size_t)10 * TT];
        float r2 = pin[(size_t)11 * TT];
        float r3 = pin[(size_t)12 * TT];
        float r4 = pin[(size_t)13 * TT];
        float r5 = pin[(size_t)14 * TT];
        float r6 = pin[(size_t)15 * TT];
        float r7 = pin[(size_t)16 * TT];

        int l0 = 1;

        // hot sub-step: no guards, e_t ready in register, LDS front-batched
        #define CRF_STEP(J, BUFC, EREG, RREG)                                  \
        {                                                                      \
            const int l = l0 + (J);                                            \
            unsigned ub = __float_as_uint(ea_f);                               \
            sh_ea[BUFC][t] = (unsigned short)((ub + 0x8000u) >> 16);           \
            float e_t = EREG;                                                  \
            EREG = __expf(RREG);               /* row l+8: 8-step-old LDG */   \
            int nrow = l + 16; nrow = (nrow < LL) ? nrow : (LL - 1);           \
            RREG = pin[(size_t)nrow * TT];     /* row l+16 */                  \
            __syncthreads();                                                   \
            const uint4* ev = reinterpret_cast<const uint4*>(sh_ea[BUFC]);     \
            uint4 v[16];                                                       \
            _Pragma("unroll")                                                  \
            for (int k = 0; k < 16; k++) v[k] = ev[k];   /* front-batched */   \
            int E = (int)((v[0].x >> 7) & 0xFFu) - 127;                        \
            float sE = __uint_as_float((unsigned)(127 - E) << 23);             \
            __nv_bfloat162 zz = __floats2bfloat162_rn(0.f, 0.f);               \
            __nv_bfloat162 a0 = zz, a1 = zz, a2 = zz, a3 = zz;                 \
            _Pragma("unroll")                                                  \
            for (int k = 0; k < 16; k++) {                                     \
                a0 = __hfma2(*reinterpret_cast<__nv_bfloat162*>(&v[k].x),      \
                             eT2[4 * k + 0], a0);                              \
                a1 = __hfma2(*reinterpret_cast<__nv_bfloat162*>(&v[k].y),      \
                             eT2[4 * k + 1], a1);                              \
                a2 = __hfma2(*reinterpret_cast<__nv_bfloat162*>(&v[k].z),      \
                             eT2[4 * k + 2], a2);                              \
                a3 = __hfma2(*reinterpret_cast<__nv_bfloat162*>(&v[k].w),      \
                             eT2[4 * k + 3], a3);                              \
            }                                                                  \
            __nv_bfloat162 s01 = __hadd2(a0, a1);                              \
            __nv_bfloat162 s23 = __hadd2(a2, a3);                              \
            __nv_bfloat162 sA  = __hadd2(s01, s23);                            \
            float2 g = __bfloat1622float2(sA);                                 \
            float acc = g.x + g.y;                                             \
            ea_f = acc * e_t * sE;                                             \
            Etot += E;                                                         \
        }

        // main loop: full-live blocks only (l0 stays ≡ 1 mod 8 -> buf = J&1)
        for (; l0 + 7 <= nsteps; l0 += 8) {
            CRF_STEP(0, 0, e0, r0)
            CRF_STEP(1, 1, e1, r1)
            CRF_STEP(2, 0, e2, r2)
            CRF_STEP(3, 1, e3, r3)
            CRF_STEP(4, 0, e4, r4)
            CRF_STEP(5, 1, e5, r5)
            CRF_STEP(6, 0, e6, r6)
            CRF_STEP(7, 1, e7, r7)
        }
        #undef CRF_STEP

        // scalar epilogue: ≤7 steps, direct loads (off the makespan path)
        for (int l = l0; l <= nsteps; l++) {
            int bufc = (l - l0) & 1 ? ((1 & 1)) : 0;      // keep alternation:
            bufc = (l + 1) & 1;                           // (l0 ≡ 1 mod 8)
            unsigned ub = __float_as_uint(ea_f);
            sh_ea[bufc][t] = (unsigned short)((ub + 0x8000u) >> 16);
            float e_t = __expf(pin[(size_t)l * TT]);
            __syncthreads();
            const uint4* ev = reinterpret_cast<const uint4*>(sh_ea[bufc]);
            int E; float sE, acc;
            {
                uint4 v0 = ev[0];
                E = (int)((v0.x >> 7) & 0xFFu) - 127;
                sE = __uint_as_float((unsigned)(127 - E) << 23);
                __nv_bfloat162 zz = __floats2bfloat162_rn(0.f, 0.f);
                __nv_bfloat162 a0 = zz, a1 = zz, a2 = zz, a3 = zz;
                a0 = __hfma2(*reinterpret_cast<__nv_bfloat162*>(&v0.x), eT2[0], a0);
                a1 = __hfma2(*reinterpret_cast<__nv_bfloat162*>(&v0.y), eT2[1], a1);
                a2 = __hfma2(*reinterpret_cast<__nv_bfloat162*>(&v0.z), eT2[2], a2);
                a3 = __hfma2(*reinterpret_cast<__nv_bfloat162*>(&v0.w), eT2[3], a3);
                #pragma unroll
                for (int k = 1; k < 16; k++) {
                    uint4 v = ev[k];
                    a0 = __hfma2(*reinterpret_cast<__nv_bfloat162*>(&v.x),
                                 eT2[4 * k + 0], a0);
                    a1 = __hfma2(*reinterpret_cast<__nv_bfloat162*>(&v.y),
                                 eT2[4 * k + 1], a1);
                    a2 = __hfma2(*reinterpret_cast<__nv_bfloat162*>(&v.z),
                                 eT2[4 * k + 2], a2);
                    a3 = __hfma2(*reinterpret_cast<__nv_bfloat162*>(&v.w),
                                 eT2[4 * k + 3], a3);
                }
                __nv_bfloat162 s01 = __hadd2(a0, a1);
                __nv_bfloat162 s23 = __hadd2(a2, a3);
                __nv_bfloat162 sA  = __hadd2(s01, s23);
                float2 g = __bfloat1622float2(sA);
                acc = g.x + g.y;
            }
            ea_f = acc * e_t * sE;
            Etot += E;
        }

        // ---- log_norm = M0 + Etot*ln2 + ln(sum_t ea_t) ----
        sh_red[t] = ea_f;
        __syncthreads();
        for (int o = 64; o > 0; o >>= 1) {
            if (t < o) sh_red[t] += sh_red[t + o];
            __syncthreads();
        }
        if (t == 0)
            out[b] = seqscore -
                     (M0 + 0.6931471805599453f * (float)Etot + __logf(sh_red[0]));
        __syncthreads();                                  // protect shared
    }
}

// ---------------------------------------------------------------------------
extern "C" void kernel_launch(void* const* d_in, const int* in_sizes, int n_in,
                              void* d_out, int out_size) {
    const float* inputs = (const float*)d_in[0];
    const int*   tags32 = (const int*)d_in[1];
    const int*   slen32 = (const int*)d_in[2];
    const float* trans  = (const float*)d_in[3];
    float* outp = (float*)d_out;

    crf_all<<<GRID, 128>>>(inputs, tags32, slen32, trans, outp);
}

// round 16
// speedup vs baseline: 2.2830x; 1.2275x over previous
#include <cuda_runtime.h>
#include <cuda_bf16.h>
#include <cstdint>

#define BB 256
#define LL 1024
#define TT 128
#define GRID 148
#define NT 160

// named barrier for the 4 compute warps only (warp 4 free-runs)
#define BAR1() asm volatile("bar.sync 1, 128;" ::: "memory")

// ---------------------------------------------------------------------------
// One fused kernel, 160 threads/CTA:
//   threads 0-127 (compute): forward recursion, sync via bar.sync 1,128
//   threads 128-159 (warp 4): sequence-score gather, overlapped, barrier-free
// Recursion (branchless, all-bf16 critical path):
//   ea_t = exp(alpha_t - M), M = M0 + ln2*Etot (exact integer Etot).
//   Per step: 16 front-batched LDS.128 -> 64 HFMA2 -> HADD2 tree ->
//   HMUL2 by e_t (bf16x2, converted off-chain in the FIFO) -> halfword
//   swap+HADD2 -> renorm by integer subtract of E<<7 in the exponent field.
//   E = bf16 exponent of ea[0] (CTA-uniform). e_t FIFO: LDG dist 16, EX2+CVT
//   dist 8. Main loop = guard-free unroll-8; scalar epilogue for the tail.
// ---------------------------------------------------------------------------
__global__ void __launch_bounds__(NT)
crf_all(const float* __restrict__ inputs,
        const int*   __restrict__ tags32,
        const int*   __restrict__ slen32,
        const float* __restrict__ trans,
        float* __restrict__ out)
{
    const int t = threadIdx.x;
    const bool comp = (t < 128);

    // int64 layout => odd words of seqlen are high words (0); int32 => >=1.
    const int stride = ((slen32[1] | slen32[3] | slen32[5] | slen32[7]) == 0) ? 2 : 1;

    __shared__ int slen[BB];
    __shared__ int inv[BB];                               // inv[rank] = batch id
    __shared__ __align__(16) unsigned short sh_ea[2][TT]; // bf16 stabilized alphas
    __shared__ float sh_red[TT];                          // reduction scratch
    __shared__ float sh_seq;                              // gather warp's result

    for (int i = t; i < BB; i += NT) {
        int v = slen32[(size_t)i * stride];
        if (v < 1) v = 1; if (v > LL) v = LL;
        slen[i] = v;
    }
    __syncthreads();

    // local LPT schedule: rank batches by descending length (unique keys)
    for (int i = t; i < BB; i += NT) {
        unsigned key_i = ((unsigned)(slen[i]) << 8) | (unsigned)i;
        int r = 0;
        for (int j = 0; j < BB; j++) {
            unsigned key_j = ((unsigned)(slen[j]) << 8) | (unsigned)j;
            r += (key_j > key_i) ? 1 : 0;
        }
        inv[r] = i;
    }

    // exp(trans) column for this thread's tag, packed bf16x2 (64 regs)
    __nv_bfloat162 eT2[TT / 2];
    if (comp) {
        #pragma unroll
        for (int k = 0; k < TT / 2; k++) {
            float e0 = __expf(trans[(2 * k + 0) * TT + t]);
            float e1 = __expf(trans[(2 * k + 1) * TT + t]);
            eT2[k] = __floats2bfloat162_rn(e0, e1);
        }
    }
    __syncthreads();                                      // inv[] ready

    // static schedule: CTA i -> rank i; CTAs 0..(BB-1-GRID) also -> rank 255-i
    const int nb = ((int)blockIdx.x <= BB - 1 - GRID) ? 2 : 1;

    for (int q = 0; q < nb; q++) {
        int rank = (q == 0) ? (int)blockIdx.x : (BB - 1 - (int)blockIdx.x);
        int b = inv[rank];
        int len = slen[b];
        int nsteps = len - 1; if (nsteps < 1) nsteps = 1;
        const float* inp = inputs + (size_t)b * LL * TT;

        float M0 = 0.f;
        int Etot = 0;

        if (!comp) {
            // ---- warp 4: sequence score gather (overlapped, no barriers) ----
            int lane = t - 128;
            const int* tg = tags32 + (size_t)b * LL * stride;
            float s = 0.f;
            for (int l = lane; l < len; l += 32) {
                int cur = tg[(size_t)l * stride] & (TT - 1);
                s += inp[(size_t)l * TT + cur];
                if (l > 0) {
                    int prev = tg[(size_t)(l - 1) * stride] & (TT - 1);
                    s += trans[prev * TT + cur];
                }
            }
            #pragma unroll
            for (int o = 16; o > 0; o >>= 1)
                s += __shfl_xor_sync(0xffffffffu, s, o);
            if (lane == 0) sh_seq = s;
        } else {
            // ---- compute warps: forward recursion ----
            const float* pin = inp + t;
            M0 = inp[0];
            unsigned short ea_h;
            {
                unsigned ub = __float_as_uint(__expf(inp[t] - M0));
                ea_h = (unsigned short)((ub + 0x8000u) >> 16);
            }

            // two-stage FIFO: eJ = bf16x2(exp(row l0+J)); rJ = raw row l0+J+8
            __nv_bfloat162 e0 = __float2bfloat162_rn(__expf(pin[(size_t)1 * TT]));
            __nv_bfloat162 e1 = __float2bfloat162_rn(__expf(pin[(size_t)2 * TT]));
            __nv_bfloat162 e2 = __float2bfloat162_rn(__expf(pin[(size_t)3 * TT]));
            __nv_bfloat162 e3 = __float2bfloat162_rn(__expf(pin[(size_t)4 * TT]));
            __nv_bfloat162 e4 = __float2bfloat162_rn(__expf(pin[(size_t)5 * TT]));
            __nv_bfloat162 e5 = __float2bfloat162_rn(__expf(pin[(size_t)6 * TT]));
            __nv_bfloat162 e6 = __float2bfloat162_rn(__expf(pin[(size_t)7 * TT]));
            __nv_bfloat162 e7 = __float2bfloat162_rn(__expf(pin[(size_t)8 * TT]));
            float r0 = pin[(size_t)9  * TT];
            float r1 = pin[(size_t)10 * TT];
            float r2 = pin[(size_t)11 * TT];
            float r3 = pin[(size_t)12 * TT];
            float r4 = pin[(size_t)13 * TT];
            float r5 = pin[(size_t)14 * TT];
            float r6 = pin[(size_t)15 * TT];
            float r7 = pin[(size_t)16 * TT];

            int l0 = 1;

            #define CRF_STEP(J, BUFC, EREG, RREG)                              \
            {                                                                  \
                const int l = l0 + (J);                                        \
                sh_ea[BUFC][t] = ea_h;                                         \
                __nv_bfloat162 e_t2 = EREG;                                    \
                EREG = __float2bfloat162_rn(__expf(RREG));                     \
                int nrow = l + 16; nrow = (nrow < LL) ? nrow : (LL - 1);       \
                RREG = pin[(size_t)nrow * TT];                                 \
                BAR1();                                                        \
                const uint4* ev = reinterpret_cast<const uint4*>(sh_ea[BUFC]); \
                uint4 v[16];                                                   \
                _Pragma("unroll")                                              \
                for (int k = 0; k < 16; k++) v[k] = ev[k];                     \
                int E = (int)((v[0].x >> 7) & 0xFFu) - 127;                    \
                __nv_bfloat162 zz = __floats2bfloat162_rn(0.f, 0.f);           \
                __nv_bfloat162 a0 = zz, a1 = zz, a2 = zz, a3 = zz;             \
                _Pragma("unroll")                                              \
                for (int k = 0; k < 16; k++) {                                 \
                    a0 = __hfma2(*reinterpret_cast<__nv_bfloat162*>(&v[k].x),  \
                                 eT2[4 * k + 0], a0);                          \
                    a1 = __hfma2(*reinterpret_cast<__nv_bfloat162*>(&v[k].y),  \
                                 eT2[4 * k + 1], a1);                          \
                    a2 = __hfma2(*reinterpret_cast<__nv_bfloat162*>(&v[k].z),  \
                                 eT2[4 * k + 2], a2);                          \
                    a3 = __hfma2(*reinterpret_cast<__nv_bfloat162*>(&v[k].w),  \
                                 eT2[4 * k + 3], a3);                          \
                }                                                              \
                __nv_bfloat162 s01 = __hadd2(a0, a1);                          \
                __nv_bfloat162 s23 = __hadd2(a2, a3);                          \
                __nv_bfloat162 sA  = __hadd2(s01, s23);                        \
                __nv_bfloat162 m   = __hmul2(sA, e_t2);                        \
                unsigned mu = *reinterpret_cast<unsigned*>(&m);                \
                unsigned sw = __byte_perm(mu, mu, 0x1032);                     \
                __nv_bfloat162 swv = *reinterpret_cast<__nv_bfloat162*>(&sw);  \
                __nv_bfloat162 r   = __hadd2(m, swv);                          \
                unsigned rb = *reinterpret_cast<unsigned*>(&r) & 0xFFFFu;      \
                ea_h = (unsigned short)(rb - (unsigned)(E << 7));              \
                Etot += E;                                                     \
            }

            for (; l0 + 7 <= nsteps; l0 += 8) {
                CRF_STEP(0, 0, e0, r0)
                CRF_STEP(1, 1, e1, r1)
                CRF_STEP(2, 0, e2, r2)
                CRF_STEP(3, 1, e3, r3)
                CRF_STEP(4, 0, e4, r4)
                CRF_STEP(5, 1, e5, r5)
                CRF_STEP(6, 0, e6, r6)
                CRF_STEP(7, 1, e7, r7)
            }
            #undef CRF_STEP

            // scalar epilogue: ≤7 steps (off-makespan), direct exp
            for (int l = l0; l <= nsteps; l++) {
                int bufc = (l + 1) & 1;                    // keeps alternation
                sh_ea[bufc][t] = ea_h;
                __nv_bfloat162 e_t2 =
                    __float2bfloat162_rn(__expf(pin[(size_t)l * TT]));
                BAR1();
                const uint4* ev = reinterpret_cast<const uint4*>(sh_ea[bufc]);
                uint4 v0 = ev[0];
                int E = (int)((v0.x >> 7) & 0xFFu) - 127;
                __nv_bfloat162 zz = __floats2bfloat162_rn(0.f, 0.f);
                __nv_bfloat162 a0 = zz, a1 = zz, a2 = zz, a3 = zz;
                a0 = __hfma2(*reinterpret_cast<__nv_bfloat162*>(&v0.x), eT2[0], a0);
                a1 = __hfma2(*reinterpret_cast<__nv_bfloat162*>(&v0.y), eT2[1], a1);
                a2 = __hfma2(*reinterpret_cast<__nv_bfloat162*>(&v0.z), eT2[2], a2);
                a3 = __hfma2(*reinterpret_cast<__nv_bfloat162*>(&v0.w), eT2[3], a3);
                #pragma unroll
                for (int k = 1; k < 16; k++) {
                    uint4 v = ev[k];
                    a0 = __hfma2(*reinterpret_cast<__nv_bfloat162*>(&v.x),
                                 eT2[4 * k + 0], a0);
                    a1 = __hfma2(*reinterpret_cast<__nv_bfloat162*>(&v.y),
                                 eT2[4 * k + 1], a1);
                    a2 = __hfma2(*reinterpret_cast<__nv_bfloat162*>(&v.z),
                                 eT2[4 * k + 2], a2);
                    a3 = __hfma2(*reinterpret_cast<__nv_bfloat162*>(&v.w),
                                 eT2[4 * k + 3], a3);
                }
                __nv_bfloat162 s01 = __hadd2(a0, a1);
                __nv_bfloat162 s23 = __hadd2(a2, a3);
                __nv_bfloat162 sA  = __hadd2(s01, s23);
                __nv_bfloat162 m   = __hmul2(sA, e_t2);
                unsigned mu = *reinterpret_cast<unsigned*>(&m);
                unsigned sw = __byte_perm(mu, mu, 0x1032);
                __nv_bfloat162 swv = *reinterpret_cast<__nv_bfloat162*>(&sw);
                __nv_bfloat162 r   = __hadd2(m, swv);
                unsigned rb = *reinterpret_cast<unsigned*>(&r) & 0xFFFFu;
                ea_h = (unsigned short)(rb - (unsigned)(E << 7));
                Etot += E;
            }

            // ---- final sum of ea over tags (fp32 tree, compute warps) ----
            sh_red[t] = __uint_as_float((unsigned)ea_h << 16);
            BAR1();
            for (int o = 64; o > 0; o >>= 1) {
                if (t < o) sh_red[t] += sh_red[t + o];
                BAR1();
            }
        }

        __syncthreads();                                  // join warp 4
        if (t == 0)
            out[b] = sh_seq -
                     (M0 + 0.6931471805599453f * (float)Etot + __logf(sh_red[0]));
        __syncthreads();                                  // protect shared
    }
}

// ---------------------------------------------------------------------------
extern "C" void kernel_launch(void* const* d_in, const int* in_sizes, int n_in,
                              void* d_out, int out_size) {
    const float* inputs = (const float*)d_in[0];
    const int*   tags32 = (const int*)d_in[1];
    const int*   slen32 = (const int*)d_in[2];
    const float* trans  = (const float*)d_in[3];
    float* outp = (float*)d_out;

    crf_all<<<GRID, NT>>>(inputs, tags32, slen32, trans, outp);
}